// round 1
// baseline (speedup 1.0000x reference)
#include <cuda_runtime.h>
#include <cstdint>

#define BATCH 4
#define DMODEL 256
#define HH 112
#define WWID 112
#define WS 7
#define NW 256      // 16x16 windows
#define LP 49       // pixels per window
#define TOPK 8
#define NHEAD 8
#define DH 32
#define SS 648      // TOPK*49 + 256
#define EPSI 1e-6f

#define FINE_TOK (TOPK*LP)     // 392
#define CHUNK 8
#define NCHUNK (FINE_TOK/CHUNK) // 49

// ---------------- scratch (device globals; no allocations allowed) ----------
__device__ float g_QF[BATCH*NW*LP*DMODEL];   // elu(q)+1, windowed [b][w][p][ch]
__device__ float g_KF[BATCH*NW*LP*DMODEL];   // elu(k)+1, windowed
__device__ float g_VN[BATCH*NW*LP*DMODEL];   // v/S, windowed
__device__ float g_qm[BATCH*NW*DMODEL];      // raw window means
__device__ float g_km[BATCH*NW*DMODEL];
__device__ float g_vm[BATCH*NW*DMODEL];
__device__ float g_KVc[BATCH*NHEAD*DH*DH];   // coarse KV (per batch,head)
__device__ float g_Ksc[BATCH*NHEAD*DH];      // coarse Ksum
__device__ int   g_idx[BATCH*NW*TOPK];

// ---------------- f32x2 helpers ----------------
__device__ __forceinline__ unsigned long long pk2(float lo, float hi){
    unsigned long long r;
    asm("mov.b64 %0, {%1, %2};" : "=l"(r) : "f"(lo), "f"(hi));
    return r;
}
__device__ __forceinline__ float2 upk2(unsigned long long x){
    float2 r;
    asm("mov.b64 {%0, %1}, %2;" : "=f"(r.x), "=f"(r.y) : "l"(x));
    return r;
}
__device__ __forceinline__ void fma2(unsigned long long &d, unsigned long long a, unsigned long long b){
    asm("fma.rn.f32x2 %0, %1, %2, %0;" : "+l"(d) : "l"(a), "l"(b));
}
__device__ __forceinline__ void cpa16(void* sdst, const void* gsrc){
    unsigned saddr = (unsigned)__cvta_generic_to_shared(sdst);
    asm volatile("cp.async.cg.shared.global [%0], [%1], 16;" :: "r"(saddr), "l"(gsrc) : "memory");
}

__device__ __forceinline__ float elu1(float x){
    return (x > 0.f) ? x + 1.f : __expf(x);
}

// ---------------- kernel 1: windowed layout + transforms + means ------------
// grid: (4*16*32, 3)   block: 256.  Each block: one (b, window-row-strip, 8-ch chunk)
__global__ void prep_kernel(const float* __restrict__ q,
                            const float* __restrict__ k,
                            const float* __restrict__ v)
{
    const int mode = blockIdx.y;
    const int bx = blockIdx.x;
    const int chnk = bx & 31;           // 32 chunks of 8 ch
    const int wi   = (bx >> 5) & 15;    // window row
    const int b    = bx >> 9;
    const int ch0  = chnk * 8;
    const float* src = (mode == 0) ? q : (mode == 1) ? k : v;
    float* dstw = (mode == 0) ? g_QF : (mode == 1) ? g_KF : g_VN;
    float* dstm = (mode == 0) ? g_qm : (mode == 1) ? g_km : g_vm;

    __shared__ float s[8*785];          // 8 ch x (7x112), padded stride 785
    const int tid = threadIdx.x;

    for (int e = tid; e < 8*784; e += 256){
        int ch = e / 784, rc = e - ch*784;
        int r = rc / 112, c = rc - r*112;
        s[ch*785 + rc] = src[((b*DMODEL + ch0 + ch)*HH + wi*7 + r)*WWID + c];
    }
    __syncthreads();

    // window means (raw values)
    if (tid < 128){
        int ch = tid & 7, wj = tid >> 3;
        float sum = 0.f;
        #pragma unroll
        for (int r = 0; r < 7; r++)
            #pragma unroll
            for (int cc = 0; cc < 7; cc++)
                sum += s[ch*785 + r*112 + wj*7 + cc];
        dstm[(b*NW + wi*16 + wj)*DMODEL + ch0 + ch] = sum * (1.f/49.f);
    }

    // windowed transformed write
    const float invS = 1.f/(float)SS;
    for (int e = tid; e < 8*784; e += 256){
        int ch = e & 7; int t = e >> 3;
        int p = t % 49, wj = t / 49;
        int r = p / 7, cc = p - r*7;
        float val = s[ch*785 + r*112 + wj*7 + cc];
        float f = (mode == 2) ? val * invS : elu1(val);
        dstw[((b*NW + wi*16 + wj)*LP + p)*DMODEL + ch0 + ch] = f;
    }
}

// ---------------- kernel 2: coarse KV + Ksum per (batch, head) --------------
// grid 32 blocks, 256 threads
__global__ void coarse_kernel()
{
    const int b = blockIdx.x >> 3, h = blockIdx.x & 7;
    const int tid = threadIdx.x;
    const int dk = tid >> 3, q4 = tid & 7;   // dv = q4*4 .. +3
    float a0=0.f,a1=0.f,a2=0.f,a3=0.f, ks=0.f;
    const float invS = 1.f/(float)SS;
    for (int w = 0; w < NW; w++){
        float kraw = g_km[(b*NW + w)*DMODEL + h*DH + dk];
        float kf = elu1(kraw);
        float4 vr = *(const float4*)&g_vm[(b*NW + w)*DMODEL + h*DH + q4*4];
        a0 += kf*vr.x; a1 += kf*vr.y; a2 += kf*vr.z; a3 += kf*vr.w;
        ks += kf;
    }
    float* o = &g_KVc[((b*NHEAD + h)*DH + dk)*DH + q4*4];
    o[0]=a0*invS; o[1]=a1*invS; o[2]=a2*invS; o[3]=a3*invS;
    if (q4 == 0) g_Ksc[(b*NHEAD + h)*DH + dk] = ks;
}

// ---------------- kernel 3: sim (qm.km^T) + top-8 per row -------------------
// grid 4*32 = 128 blocks, 256 threads; each block: 8 query rows
__global__ void simtopk_kernel()
{
    const int b = blockIdx.x >> 5;
    const int qr0 = (blockIdx.x & 31) * 8;
    const int tid = threadIdx.x;
    __shared__ float qsh[8*256];     // later reused as sim rows
    __shared__ float ksh[256*33];

    for (int e = tid; e < 2048; e += 256){
        int r = e >> 8, ch = e & 255;
        qsh[e - (ch) + ch] = 0.f; // no-op to keep compiler honest
        qsh[r*256 + ch] = g_qm[(b*NW + qr0 + r)*DMODEL + ch];
    }
    float acc[8];
    #pragma unroll
    for (int r = 0; r < 8; r++) acc[r] = 0.f;

    for (int ct = 0; ct < 8; ct++){
        __syncthreads();
        int ch0 = ct * 32;
        for (int e = tid; e < 8192; e += 256){
            int row = e >> 5, ch = e & 31;
            ksh[row*33 + ch] = g_km[(b*NW + row)*DMODEL + ch0 + ch];
        }
        __syncthreads();
        #pragma unroll
        for (int ch = 0; ch < 32; ch++){
            float kv = ksh[tid*33 + ch];
            #pragma unroll
            for (int r = 0; r < 8; r++)
                acc[r] += qsh[r*256 + ch0 + ch] * kv;
        }
    }
    __syncthreads();
    #pragma unroll
    for (int r = 0; r < 8; r++) qsh[r*256 + tid] = acc[r];   // sim rows
    __syncthreads();

    // top-8 per row: warp w handles row w
    int w = tid >> 5, lane = tid & 31;
    float* row = &qsh[w*256];
    for (int j = 0; j < TOPK; j++){
        float lv = -3.0e38f; int li = 1 << 30;
        for (int c = lane; c < 256; c += 32){
            float v2 = row[c];
            if (v2 > lv) { lv = v2; li = c; }
        }
        #pragma unroll
        for (int off = 16; off; off >>= 1){
            float ov = __shfl_down_sync(0xffffffffu, lv, off);
            int   oi = __shfl_down_sync(0xffffffffu, li, off);
            if (ov > lv || (ov == lv && oi < li)) { lv = ov; li = oi; }
        }
        li = __shfl_sync(0xffffffffu, li, 0);
        if (lane == 0){
            g_idx[(b*NW + qr0 + w)*TOPK + j] = li;
            row[li] = -3.0e38f;
        }
        __syncwarp();
    }
}

// ---------------- kernel 4: per-window linear attention ---------------------
// grid 1024 (b*qw), block 256.  warp = head.  f32x2 rank-1 KV accumulation.
// dynamic smem union: staging (3 x 8tok x 256 x {KF,VN}) vs epilogue buffers.
#define EPI_KV   0
#define EPI_KS   8192
#define EPI_Z    8448
#define EPI_MSG  8848
#define ATTN_SMEM_FLOATS (EPI_MSG + LP*DMODEL)   // 8848 + 12544 = 21392
#define ATTN_SMEM_BYTES  (ATTN_SMEM_FLOATS*4)    // 85568

__global__ void __launch_bounds__(256, 2) attn_kernel(float* __restrict__ out)
{
    const int b  = blockIdx.x >> 8;
    const int qw = blockIdx.x & 255;
    const int tid = threadIdx.x;
    const int h = tid >> 5, lane = tid & 31;
    const int gdk = lane >> 2, gdv = lane & 3;
    const int dk0 = gdk * 4, dv0 = gdv * 8;

    extern __shared__ float dsm[];
    float* kfb = dsm;                      // [3][CHUNK][256]
    float* vnb = dsm + 3*CHUNK*DMODEL;     // [3][CHUNK][256]
    __shared__ int sb[FINE_TOK];
    __shared__ int widx[TOPK];

    if (tid < TOPK) widx[tid] = g_idx[(b*NW + qw)*TOPK + tid];
    __syncthreads();
    for (int s2 = tid; s2 < FINE_TOK; s2 += 256){
        int j = s2 / 49, p = s2 - j*49;
        sb[s2] = ((b*NW + widx[j])*LP + p) * DMODEL;
    }
    __syncthreads();

    auto load_chunk = [&](int c){
        int buf = c % 3;
        #pragma unroll
        for (int it = 0; it < 4; it++){
            int e = tid + it*256;           // 0..1023 float4 slots
            int arr = e >> 9;
            int r = e & 511;
            int sl = r >> 6;
            int c4 = (r & 63) * 4;
            const float* gsrc = (arr ? g_VN : g_KF) + sb[c*CHUNK + sl] + c4;
            float* sdst = (arr ? vnb : kfb) + (buf*CHUNK + sl)*DMODEL + c4;
            cpa16(sdst, gsrc);
        }
        asm volatile("cp.async.commit_group;" ::: "memory");
    };

    // init accumulators from coarse KV / Ksum
    unsigned long long acc[4][4];
    float ks0, ks1, ks2v, ks3;
    {
        const float* kvp = &g_KVc[((b*NHEAD + h)*DH + dk0)*DH + dv0];
        #pragma unroll
        for (int i = 0; i < 4; i++)
            #pragma unroll
            for (int j = 0; j < 4; j++){
                float2 v2 = *(const float2*)(kvp + i*DH + 2*j);
                acc[i][j] = pk2(v2.x, v2.y);
            }
        float4 kini = *(const float4*)&g_Ksc[(b*NHEAD + h)*DH + dk0];
        ks0 = kini.x; ks1 = kini.y; ks2v = kini.z; ks3 = kini.w;
    }

    load_chunk(0);
    load_chunk(1);

    for (int c = 0; c < NCHUNK; c++){
        asm volatile("cp.async.wait_group 1;" ::: "memory");
        __syncthreads();
        if (c + 2 < NCHUNK) load_chunk(c + 2);
        else asm volatile("cp.async.commit_group;" ::: "memory");

        int buf = c % 3;
        const float* kfp = kfb + buf*CHUNK*DMODEL + h*DH + dk0;
        const float* vnp = vnb + buf*CHUNK*DMODEL + h*DH + dv0;
        #pragma unroll
        for (int s2 = 0; s2 < CHUNK; s2++){
            float4 kf4 = *(const float4*)(kfp + s2*DMODEL);
            ulonglong2 va = *(const ulonglong2*)(vnp + s2*DMODEL);
            ulonglong2 vb = *(const ulonglong2*)(vnp + s2*DMODEL + 4);
            unsigned long long kp;
            kp = pk2(kf4.x, kf4.x);
            fma2(acc[0][0], kp, va.x); fma2(acc[0][1], kp, va.y);
            fma2(acc[0][2], kp, vb.x); fma2(acc[0][3], kp, vb.y);
            kp = pk2(kf4.y, kf4.y);
            fma2(acc[1][0], kp, va.x); fma2(acc[1][1], kp, va.y);
            fma2(acc[1][2], kp, vb.x); fma2(acc[1][3], kp, vb.y);
            kp = pk2(kf4.z, kf4.z);
            fma2(acc[2][0], kp, va.x); fma2(acc[2][1], kp, va.y);
            fma2(acc[2][2], kp, vb.x); fma2(acc[2][3], kp, vb.y);
            kp = pk2(kf4.w, kf4.w);
            fma2(acc[3][0], kp, va.x); fma2(acc[3][1], kp, va.y);
            fma2(acc[3][2], kp, vb.x); fma2(acc[3][3], kp, vb.y);
            ks0 += kf4.x; ks1 += kf4.y; ks2v += kf4.z; ks3 += kf4.w;
        }
    }

    asm volatile("cp.async.wait_group 0;" ::: "memory");
    __syncthreads();   // everyone done reading staging; reuse dsm for epilogue

    float* KVsh  = dsm + EPI_KV;    // [8][32][32]
    float* Kssh  = dsm + EPI_KS;    // [8][32]
    float* Zsh   = dsm + EPI_Z;     // [49][8]
    float* msgsh = dsm + EPI_MSG;   // [49][256]

    #pragma unroll
    for (int i = 0; i < 4; i++)
        #pragma unroll
        for (int j = 0; j < 4; j++){
            float2 v2 = upk2(acc[i][j]);
            *(float2*)&KVsh[(h*DH + dk0 + i)*DH + dv0 + 2*j] = v2;
        }
    if (gdv == 0){
        Kssh[h*DH + dk0 + 0] = ks0;
        Kssh[h*DH + dk0 + 1] = ks1;
        Kssh[h*DH + dk0 + 2] = ks2v;
        Kssh[h*DH + dk0 + 3] = ks3;
    }
    __syncthreads();

    const float* qfbase = &g_QF[(b*NW + qw)*LP*DMODEL];

    // Z per (l, head)
    for (int pr = tid; pr < LP*NHEAD; pr += 256){
        int l = pr >> 3, hh = pr & 7;
        const float* qf = qfbase + l*DMODEL + hh*DH;
        float dot = 0.f;
        #pragma unroll
        for (int t = 0; t < 8; t++){
            float4 q4 = *(const float4*)(qf + t*4);
            const float* kr = &Kssh[hh*DH + t*4];
            dot += q4.x*kr[0] + q4.y*kr[1] + q4.z*kr[2] + q4.w*kr[3];
        }
        Zsh[l*NHEAD + hh] = 1.f/(dot + EPSI);
    }
    __syncthreads();

    // msg: thread = channel; KV column cached in regs
    {
        int dv = lane;
        float kvc[32];
        #pragma unroll
        for (int dk = 0; dk < 32; dk++) kvc[dk] = KVsh[(h*DH + dk)*DH + dv];
        for (int l = 0; l < LP; l++){
            const float* qf = qfbase + l*DMODEL + h*DH;
            float m2 = 0.f;
            #pragma unroll
            for (int t = 0; t < 8; t++){
                float4 q4 = *(const float4*)(qf + t*4);
                m2 += q4.x*kvc[t*4] + q4.y*kvc[t*4+1] + q4.z*kvc[t*4+2] + q4.w*kvc[t*4+3];
            }
            msgsh[l*DMODEL + tid] = m2 * Zsh[l*NHEAD + h] * (float)SS;
        }
    }
    __syncthreads();

    // write out: thread = channel, 7-float contiguous runs
    {
        int mi = qw >> 4, ni = qw & 15;
        float* ob = out + ((b*DMODEL + tid)*HH + mi*7)*WWID + ni*7;
        #pragma unroll
        for (int r = 0; r < 7; r++){
            #pragma unroll
            for (int cc = 0; cc < 7; cc++)
                ob[r*WWID + cc] = msgsh[(r*7 + cc)*DMODEL + tid];
        }
    }
}

// ---------------- launch -----------------------------------------------------
extern "C" void kernel_launch(void* const* d_in, const int* in_sizes, int n_in,
                              void* d_out, int out_size)
{
    const float* q = (const float*)d_in[0];
    const float* k = (const float*)d_in[1];
    const float* v = (const float*)d_in[2];
    float* out = (float*)d_out;

    cudaFuncSetAttribute(attn_kernel, cudaFuncAttributeMaxDynamicSharedMemorySize,
                         ATTN_SMEM_BYTES);

    prep_kernel<<<dim3(2048, 3), 256>>>(q, k, v);
    coarse_kernel<<<32, 256>>>();
    simtopk_kernel<<<128, 256>>>();
    attn_kernel<<<BATCH*NW, 256, ATTN_SMEM_BYTES>>>(out);
}

// round 3
// speedup vs baseline: 1.1442x; 1.1442x over previous
#include <cuda_runtime.h>
#include <cstdint>

#define BATCH 4
#define DMODEL 256
#define HH 112
#define WWID 112
#define NW 256      // 16x16 windows
#define LP 49
#define TOPK 8
#define NHEAD 8
#define DH 32
#define SS 648
#define EPSI 1e-6f

// ---------------- scratch ----------------
__device__ float g_QF[BATCH*NW*LP*DMODEL];   // elu(q)+1 windowed [bw][p][ch]
__device__ float g_KF[BATCH*NW*LP*DMODEL];   // elu(k)+1 windowed
__device__ float g_VN[BATCH*NW*LP*DMODEL];   // v/S windowed
__device__ float g_qm[BATCH*NW*DMODEL];
__device__ float g_km[BATCH*NW*DMODEL];
__device__ float g_vm[BATCH*NW*DMODEL];
__device__ float g_KVw[(size_t)BATCH*NW*NHEAD*DH*DH];  // 33.5MB per-window KV (from v/S)
__device__ float g_Ksw[BATCH*NW*DMODEL];               // per-window kf sums (raw)
__device__ float g_KVc[BATCH*NHEAD*DH*DH];             // coarse KV (already /S)
__device__ float g_Ksc[BATCH*NHEAD*DH];                // coarse kf sum (raw)
__device__ int   g_idx[BATCH*NW*TOPK];

// ---------------- helpers ----------------
__device__ __forceinline__ unsigned long long pk2(float lo, float hi){
    unsigned long long r;
    asm("mov.b64 %0, {%1, %2};" : "=l"(r) : "f"(lo), "f"(hi));
    return r;
}
__device__ __forceinline__ float2 upk2(unsigned long long x){
    float2 r;
    asm("mov.b64 {%0, %1}, %2;" : "=f"(r.x), "=f"(r.y) : "l"(x));
    return r;
}
__device__ __forceinline__ void fma2(unsigned long long &d, unsigned long long a, unsigned long long b){
    asm("fma.rn.f32x2 %0, %1, %2, %0;" : "+l"(d) : "l"(a), "l"(b));
}
__device__ __forceinline__ float elu1(float x){
    return (x > 0.f) ? x + 1.f : __expf(x);
}

// ---------------- kernel 1: windowed layout + transforms + means ------------
// grid (2048, 3), block 256. block = (b, window-row-strip, 8-ch chunk)
#define SP 792
__global__ void prep_kernel(const float* __restrict__ q,
                            const float* __restrict__ k,
                            const float* __restrict__ v)
{
    const int mode = blockIdx.y;
    const int bx = blockIdx.x;
    const int chnk = bx & 31;
    const int wi   = (bx >> 5) & 15;
    const int b    = bx >> 9;
    const int ch0  = chnk * 8;
    const float* src = (mode == 0) ? q : (mode == 1) ? k : v;
    float* dstw = (mode == 0) ? g_QF : (mode == 1) ? g_KF : g_VN;
    float* dstm = (mode == 0) ? g_qm : (mode == 1) ? g_km : g_vm;

    __shared__ float s[8*SP];
    const int tid = threadIdx.x;

    // the 7x112 strip per channel is 784 contiguous floats, 16B aligned
    for (int e = tid; e < 8*196; e += 256){
        int ch = e / 196, i4 = e - ch*196;
        const float4* gp = (const float4*)(src + (size_t)(b*DMODEL + ch0 + ch)*HH*WWID
                                           + (size_t)wi*784) + i4;
        *(float4*)&s[ch*SP + i4*4] = *gp;
    }
    __syncthreads();

    if (tid < 128){
        int ch = tid & 7, wj = tid >> 3;
        float sum = 0.f;
        #pragma unroll
        for (int r = 0; r < 7; r++)
            #pragma unroll
            for (int cc = 0; cc < 7; cc++)
                sum += s[ch*SP + r*112 + wj*7 + cc];
        dstm[(b*NW + wi*16 + wj)*DMODEL + ch0 + ch] = sum * (1.f/49.f);
    }

    const float invS = 1.f/(float)SS;
    for (int e = tid; e < 784; e += 256){
        int wj = e / 49, p = e - wj*49;
        int r = p / 7, cc = p - r*7;
        float vv[8];
        #pragma unroll
        for (int ch = 0; ch < 8; ch++){
            float x = s[ch*SP + r*112 + wj*7 + cc];
            vv[ch] = (mode == 2) ? x * invS : elu1(x);
        }
        float* dp = dstw + ((size_t)(b*NW + wi*16 + wj)*LP + p)*DMODEL + ch0;
        *(float4*)dp     = make_float4(vv[0], vv[1], vv[2], vv[3]);
        *(float4*)(dp+4) = make_float4(vv[4], vv[5], vv[6], vv[7]);
    }
}

// ---------------- kernel 2: per-window KV + Ksum -----------------------------
// grid 1024 (b*w), block 256, warp = head. acc = Sum_p kf[p,dk] * vn[p,dv]
__global__ void __launch_bounds__(256) windowkv_kernel()
{
    const int bw = blockIdx.x;
    const int tid = threadIdx.x;
    const int h = tid >> 5, lane = tid & 31;
    const int dk0 = (lane >> 2) * 4, dv0 = (lane & 3) * 8;

    const float* kf = g_KF + (size_t)bw*LP*DMODEL + h*DH + dk0;
    const float* vn = g_VN + (size_t)bw*LP*DMODEL + h*DH + dv0;

    unsigned long long acc[4][4];
    #pragma unroll
    for (int i = 0; i < 4; i++)
        #pragma unroll
        for (int j = 0; j < 4; j++) acc[i][j] = 0ull;
    float s0=0.f, s1=0.f, s2=0.f, s3=0.f;

    #pragma unroll 7
    for (int p = 0; p < LP; p++){
        float4 kf4 = *(const float4*)(kf + (size_t)p*DMODEL);
        ulonglong2 va = *(const ulonglong2*)(vn + (size_t)p*DMODEL);
        ulonglong2 vb = *(const ulonglong2*)(vn + (size_t)p*DMODEL + 4);
        unsigned long long kp;
        kp = pk2(kf4.x, kf4.x);
        fma2(acc[0][0], kp, va.x); fma2(acc[0][1], kp, va.y);
        fma2(acc[0][2], kp, vb.x); fma2(acc[0][3], kp, vb.y);
        kp = pk2(kf4.y, kf4.y);
        fma2(acc[1][0], kp, va.x); fma2(acc[1][1], kp, va.y);
        fma2(acc[1][2], kp, vb.x); fma2(acc[1][3], kp, vb.y);
        kp = pk2(kf4.z, kf4.z);
        fma2(acc[2][0], kp, va.x); fma2(acc[2][1], kp, va.y);
        fma2(acc[2][2], kp, vb.x); fma2(acc[2][3], kp, vb.y);
        kp = pk2(kf4.w, kf4.w);
        fma2(acc[3][0], kp, va.x); fma2(acc[3][1], kp, va.y);
        fma2(acc[3][2], kp, vb.x); fma2(acc[3][3], kp, vb.y);
        s0 += kf4.x; s1 += kf4.y; s2 += kf4.z; s3 += kf4.w;
    }

    float* o = g_KVw + (size_t)bw*(NHEAD*DH*DH) + h*DH*DH + dk0*DH + dv0;
    #pragma unroll
    for (int i = 0; i < 4; i++)
        #pragma unroll
        for (int j = 0; j < 4; j++){
            float2 t = upk2(acc[i][j]);
            *(float2*)(o + i*DH + 2*j) = t;
        }
    if ((lane & 3) == 0){
        float* ks = g_Ksw + bw*DMODEL + h*DH + dk0;
        ks[0]=s0; ks[1]=s1; ks[2]=s2; ks[3]=s3;
    }
}

// ---------------- kernel 3: coarse KV + Ksum per (batch, head) --------------
__global__ void coarse_kernel()
{
    const int b = blockIdx.x >> 3, h = blockIdx.x & 7;
    const int tid = threadIdx.x;
    const int dk = tid >> 3, q4 = tid & 7;
    float a0=0.f,a1=0.f,a2=0.f,a3=0.f, ks=0.f;
    const float invS = 1.f/(float)SS;
    for (int w = 0; w < NW; w++){
        float kraw = g_km[(b*NW + w)*DMODEL + h*DH + dk];
        float kf = elu1(kraw);
        float4 vr = *(const float4*)&g_vm[(b*NW + w)*DMODEL + h*DH + q4*4];
        a0 += kf*vr.x; a1 += kf*vr.y; a2 += kf*vr.z; a3 += kf*vr.w;
        ks += kf;
    }
    float* o = &g_KVc[((b*NHEAD + h)*DH + dk)*DH + q4*4];
    o[0]=a0*invS; o[1]=a1*invS; o[2]=a2*invS; o[3]=a3*invS;
    if (q4 == 0) g_Ksc[(b*NHEAD + h)*DH + dk] = ks;
}

// ---------------- kernel 4: sim + top-8 --------------------------------------
__global__ void simtopk_kernel()
{
    const int b = blockIdx.x >> 5;
    const int qr0 = (blockIdx.x & 31) * 8;
    const int tid = threadIdx.x;
    __shared__ float qsh[8*256];
    __shared__ float ksh[256*33];

    for (int e = tid; e < 2048; e += 256){
        int r = e >> 8, ch = e & 255;
        qsh[r*256 + ch] = g_qm[(b*NW + qr0 + r)*DMODEL + ch];
    }
    float acc[8];
    #pragma unroll
    for (int r = 0; r < 8; r++) acc[r] = 0.f;

    for (int ct = 0; ct < 8; ct++){
        __syncthreads();
        int ch0 = ct * 32;
        for (int e = tid; e < 8192; e += 256){
            int row = e >> 5, ch = e & 31;
            ksh[row*33 + ch] = g_km[(b*NW + row)*DMODEL + ch0 + ch];
        }
        __syncthreads();
        #pragma unroll
        for (int ch = 0; ch < 32; ch++){
            float kv = ksh[tid*33 + ch];
            #pragma unroll
            for (int r = 0; r < 8; r++)
                acc[r] += qsh[r*256 + ch0 + ch] * kv;
        }
    }
    __syncthreads();
    #pragma unroll
    for (int r = 0; r < 8; r++) qsh[r*256 + tid] = acc[r];
    __syncthreads();

    int w = tid >> 5, lane = tid & 31;
    float* row = &qsh[w*256];
    for (int j = 0; j < TOPK; j++){
        float lv = -3.0e38f; int li = 1 << 30;
        for (int c = lane; c < 256; c += 32){
            float v2 = row[c];
            if (v2 > lv) { lv = v2; li = c; }
        }
        #pragma unroll
        for (int off = 16; off; off >>= 1){
            float ov = __shfl_down_sync(0xffffffffu, lv, off);
            int   oi = __shfl_down_sync(0xffffffffu, li, off);
            if (ov > lv || (ov == lv && oi < li)) { lv = ov; li = oi; }
        }
        li = __shfl_sync(0xffffffffu, li, 0);
        if (lane == 0){
            g_idx[(b*NW + qr0 + w)*TOPK + j] = li;
            row[li] = -3.0e38f;
        }
        __syncwarp();
    }
}

// ---------------- kernel 5: gather-sum KV + epilogue --------------------------
__global__ void __launch_bounds__(256) attn_kernel(float* __restrict__ out)
{
    __shared__ float KVsh[NHEAD*DH*DH];   // 8192 floats
    __shared__ float Kssh[DMODEL];
    __shared__ float Zsh[LP*NHEAD];
    __shared__ int widx[TOPK];

    const int b  = blockIdx.x >> 8;
    const int qw = blockIdx.x & 255;
    const int tid = threadIdx.x;
    const int h = tid >> 5, lane = tid & 31;

    if (tid < TOPK) widx[tid] = g_idx[(b*NW + qw)*TOPK + tid];
    __syncthreads();

    // Ksum gather (coarse raw + fine raw)
    {
        float ks = g_Ksc[b*DMODEL + tid];
        #pragma unroll
        for (int j = 0; j < TOPK; j++)
            ks += g_Ksw[(b*NW + widx[j])*DMODEL + tid];
        Kssh[tid] = ks;
    }

    // KV gather-sum: KV = KVc + Sum_j KVw[widx_j]
    // (KVw already built from v/S, KVc already /S -> plain sum)
    const float4* cb = (const float4*)g_KVc + b*2048;
    #pragma unroll
    for (int it = 0; it < 8; it++){
        int t = tid + it*256;
        float ax=0.f, ay=0.f, az=0.f, aw=0.f;
        #pragma unroll
        for (int j = 0; j < TOPK; j++){
            float4 x = *((const float4*)g_KVw + (size_t)(b*NW + widx[j])*2048 + t);
            ax += x.x; ay += x.y; az += x.z; aw += x.w;
        }
        float4 c = cb[t];
        ((float4*)KVsh)[t] = make_float4(c.x + ax, c.y + ay,
                                         c.z + az, c.w + aw);
    }
    __syncthreads();

    const float* qfbase = &g_QF[(size_t)(b*NW + qw)*LP*DMODEL];

    // Z per (l, head)
    for (int pr = tid; pr < LP*NHEAD; pr += 256){
        int l = pr >> 3, hh = pr & 7;
        const float* qf = qfbase + l*DMODEL + hh*DH;
        float dot = 0.f;
        #pragma unroll
        for (int t = 0; t < 8; t++){
            float4 q4 = *(const float4*)(qf + t*4);
            const float* kr = &Kssh[hh*DH + t*4];
            dot += q4.x*kr[0] + q4.y*kr[1] + q4.z*kr[2] + q4.w*kr[3];
        }
        Zsh[l*NHEAD + hh] = 1.f/(dot + EPSI);
    }
    __syncthreads();

    // msg: thread = channel (h = tid>>5, dv = lane), KV column packed in regs
    {
        unsigned long long kvc[16];
        #pragma unroll
        for (int t = 0; t < 16; t++)
            kvc[t] = pk2(KVsh[(h*DH + 2*t)*DH + lane],
                         KVsh[(h*DH + 2*t+1)*DH + lane]);

        const int mi = qw >> 4, ni = qw & 15;
        float* ob = out + ((size_t)(b*DMODEL + tid)*HH + mi*7)*WWID + ni*7;

        for (int r = 0; r < 7; r++){
            #pragma unroll
            for (int cc = 0; cc < 7; cc++){
                int l = r*7 + cc;
                const float* qf = qfbase + l*DMODEL + h*DH;
                unsigned long long a2 = 0ull;
                #pragma unroll
                for (int t = 0; t < 8; t++){
                    float4 q4 = *(const float4*)(qf + t*4);
                    fma2(a2, pk2(q4.x, q4.y), kvc[2*t]);
                    fma2(a2, pk2(q4.z, q4.w), kvc[2*t+1]);
                }
                float2 p2 = upk2(a2);
                ob[r*WWID + cc] = (p2.x + p2.y) * Zsh[l*NHEAD + h] * (float)SS;
            }
        }
    }
}

// ---------------- launch ------------------------------------------------------
extern "C" void kernel_launch(void* const* d_in, const int* in_sizes, int n_in,
                              void* d_out, int out_size)
{
    const float* q = (const float*)d_in[0];
    const float* k = (const float*)d_in[1];
    const float* v = (const float*)d_in[2];
    float* out = (float*)d_out;

    prep_kernel<<<dim3(2048, 3), 256>>>(q, k, v);
    windowkv_kernel<<<BATCH*NW, 256>>>();
    coarse_kernel<<<32, 256>>>();
    simtopk_kernel<<<128, 256>>>();
    attn_kernel<<<BATCH*NW, 256>>>(out);
}

// round 4
// speedup vs baseline: 1.2601x; 1.1013x over previous
#include <cuda_runtime.h>
#include <cstdint>

#define BATCH 4
#define DMODEL 256
#define HH 112
#define WWID 112
#define NPIX (HH*WWID)    // 12544
#define NW 256
#define LP 49
#define TOPK 8
#define NHEAD 8
#define DH 32
#define SS 648
#define EPSI 1e-6f

// ---------------- scratch (pixel-major [b][px][256]) ----------------
__device__ float g_QF[(size_t)BATCH*NPIX*DMODEL];   // elu(q)+1
__device__ float g_KF[(size_t)BATCH*NPIX*DMODEL];   // elu(k)+1
__device__ float g_VN[(size_t)BATCH*NPIX*DMODEL];   // v/S
__device__ float g_OUT[(size_t)BATCH*NPIX*DMODEL];  // msg, pixel-major
__device__ float g_qm[BATCH*NW*DMODEL];
__device__ float g_km[BATCH*NW*DMODEL];
__device__ float g_vm[BATCH*NW*DMODEL];
__device__ float g_KVw[(size_t)BATCH*NW*NHEAD*DH*DH];  // per-window KV (v/S side)
__device__ float g_Ksw[BATCH*NW*DMODEL];               // per-window kf sums
__device__ float g_KVc[BATCH*NHEAD*DH*DH];             // coarse KV (already /S)
__device__ float g_Ksc[BATCH*NHEAD*DH];                // coarse kf sum
__device__ int   g_idx[BATCH*NW*TOPK];

// ---------------- helpers ----------------
__device__ __forceinline__ unsigned long long pk2(float lo, float hi){
    unsigned long long r;
    asm("mov.b64 %0, {%1, %2};" : "=l"(r) : "f"(lo), "f"(hi));
    return r;
}
__device__ __forceinline__ float2 upk2(unsigned long long x){
    float2 r;
    asm("mov.b64 {%0, %1}, %2;" : "=f"(r.x), "=f"(r.y) : "l"(x));
    return r;
}
__device__ __forceinline__ void fma2(unsigned long long &d, unsigned long long a, unsigned long long b){
    asm("fma.rn.f32x2 %0, %1, %2, %0;" : "+l"(d) : "l"(a), "l"(b));
}
__device__ __forceinline__ float elu1(float x){
    return (x > 0.f) ? x + 1.f : __expf(x);
}

// ---------------- kernel 1: in-transpose [b][ch][px] -> [b][px][ch] + transform
// grid (392, 4, 3) block 256; tile = 32 px x 256 ch
__global__ void __launch_bounds__(256) transpose_in_kernel(
    const float* __restrict__ q, const float* __restrict__ k,
    const float* __restrict__ v)
{
    const int mode = blockIdx.z, b = blockIdx.y;
    const int px0 = blockIdx.x * 32;
    const float* src = (mode == 0) ? q : (mode == 1) ? k : v;
    float* dst = (mode == 0) ? g_QF : (mode == 1) ? g_KF : g_VN;

    __shared__ float s[256*33];
    const int tid = threadIdx.x;
    const float invS = 1.f/(float)SS;

    // load float4 over px: lanes cover (ch, px4), 128B-coalesced
    #pragma unroll
    for (int i = 0; i < 8; i++){
        int e = tid + i*256;              // 0..2047 float4 slots
        int ch = e >> 3, px4 = (e & 7) * 4;
        float4 x = *(const float4*)(src + (size_t)(b*DMODEL + ch)*NPIX + px0 + px4);
        float f0, f1, f2, f3;
        if (mode == 2){ f0 = x.x*invS; f1 = x.y*invS; f2 = x.z*invS; f3 = x.w*invS; }
        else { f0 = elu1(x.x); f1 = elu1(x.y); f2 = elu1(x.z); f3 = elu1(x.w); }
        s[ch*33 + px4 + 0] = f0;
        s[ch*33 + px4 + 1] = f1;
        s[ch*33 + px4 + 2] = f2;
        s[ch*33 + px4 + 3] = f3;
    }
    __syncthreads();
    // store: lanes cover consecutive ch -> 128B-coalesced
    #pragma unroll
    for (int i = 0; i < 32; i++){
        int e = tid + i*256;              // 0..8191
        int px = e >> 8, ch = e & 255;
        dst[(size_t)(b*NPIX + px0 + px)*DMODEL + ch] = s[ch*33 + px];
    }
}

// ---------------- kernel 2: raw window means --------------------------------
// grid (2048, 3) block 256: (b, window-row strip, 8-ch chunk)
#define SP 792
__global__ void means_kernel(const float* __restrict__ q,
                             const float* __restrict__ k,
                             const float* __restrict__ v)
{
    const int mode = blockIdx.y;
    const int bx = blockIdx.x;
    const int chnk = bx & 31;
    const int wi   = (bx >> 5) & 15;
    const int b    = bx >> 9;
    const int ch0  = chnk * 8;
    const float* src = (mode == 0) ? q : (mode == 1) ? k : v;
    float* dstm = (mode == 0) ? g_qm : (mode == 1) ? g_km : g_vm;

    __shared__ float s[8*SP];
    const int tid = threadIdx.x;

    for (int e = tid; e < 8*196; e += 256){
        int ch = e / 196, i4 = e - ch*196;
        const float4* gp = (const float4*)(src + (size_t)(b*DMODEL + ch0 + ch)*NPIX
                                           + (size_t)wi*784) + i4;
        *(float4*)&s[ch*SP + i4*4] = *gp;
    }
    __syncthreads();

    if (tid < 128){
        int ch = tid & 7, wj = tid >> 3;
        float sum = 0.f;
        #pragma unroll
        for (int r = 0; r < 7; r++)
            #pragma unroll
            for (int cc = 0; cc < 7; cc++)
                sum += s[ch*SP + r*112 + wj*7 + cc];
        dstm[(b*NW + wi*16 + wj)*DMODEL + ch0 + ch] = sum * (1.f/49.f);
    }
}

// ---------------- kernel 3: per-window KV + Ksum ----------------------------
// grid 1024 (b*w), block 256, warp = head
__global__ void __launch_bounds__(256) windowkv_kernel()
{
    const int bw = blockIdx.x;
    const int b = bw >> 8, w = bw & 255;
    const int mi = w >> 4, ni = w & 15;
    const int tid = threadIdx.x;
    const int h = tid >> 5, lane = tid & 31;
    const int dk0 = (lane >> 2) * 4, dv0 = (lane & 3) * 8;

    const size_t base = (size_t)(b*NPIX + (mi*7)*WWID + ni*7) * DMODEL;
    const float* kf = g_KF + base + h*DH + dk0;
    const float* vn = g_VN + base + h*DH + dv0;

    unsigned long long acc[4][4];
    #pragma unroll
    for (int i = 0; i < 4; i++)
        #pragma unroll
        for (int j = 0; j < 4; j++) acc[i][j] = 0ull;
    float s0=0.f, s1=0.f, s2=0.f, s3=0.f;

    #pragma unroll
    for (int r = 0; r < 7; r++){
        #pragma unroll
        for (int cc = 0; cc < 7; cc++){
            const size_t off = (size_t)(r*WWID + cc)*DMODEL;
            float4 kf4 = *(const float4*)(kf + off);
            ulonglong2 va = *(const ulonglong2*)(vn + off);
            ulonglong2 vb = *(const ulonglong2*)(vn + off + 4);
            unsigned long long kp;
            kp = pk2(kf4.x, kf4.x);
            fma2(acc[0][0], kp, va.x); fma2(acc[0][1], kp, va.y);
            fma2(acc[0][2], kp, vb.x); fma2(acc[0][3], kp, vb.y);
            kp = pk2(kf4.y, kf4.y);
            fma2(acc[1][0], kp, va.x); fma2(acc[1][1], kp, va.y);
            fma2(acc[1][2], kp, vb.x); fma2(acc[1][3], kp, vb.y);
            kp = pk2(kf4.z, kf4.z);
            fma2(acc[2][0], kp, va.x); fma2(acc[2][1], kp, va.y);
            fma2(acc[2][2], kp, vb.x); fma2(acc[2][3], kp, vb.y);
            kp = pk2(kf4.w, kf4.w);
            fma2(acc[3][0], kp, va.x); fma2(acc[3][1], kp, va.y);
            fma2(acc[3][2], kp, vb.x); fma2(acc[3][3], kp, vb.y);
            s0 += kf4.x; s1 += kf4.y; s2 += kf4.z; s3 += kf4.w;
        }
    }

    float* o = g_KVw + (size_t)bw*(NHEAD*DH*DH) + h*DH*DH + dk0*DH + dv0;
    #pragma unroll
    for (int i = 0; i < 4; i++)
        #pragma unroll
        for (int j = 0; j < 4; j++){
            float2 t = upk2(acc[i][j]);
            *(float2*)(o + i*DH + 2*j) = t;
        }
    if ((lane & 3) == 0){
        float* ks = g_Ksw + bw*DMODEL + h*DH + dk0;
        ks[0]=s0; ks[1]=s1; ks[2]=s2; ks[3]=s3;
    }
}

// ---------------- kernel 4: coarse KV + Ksum per (batch, head) --------------
__global__ void coarse_kernel()
{
    const int b = blockIdx.x >> 3, h = blockIdx.x & 7;
    const int tid = threadIdx.x;
    const int dk = tid >> 3, q4 = tid & 7;
    float a0=0.f,a1=0.f,a2=0.f,a3=0.f, ks=0.f;
    const float invS = 1.f/(float)SS;
    for (int w = 0; w < NW; w++){
        float kraw = g_km[(b*NW + w)*DMODEL + h*DH + dk];
        float kf = elu1(kraw);
        float4 vr = *(const float4*)&g_vm[(b*NW + w)*DMODEL + h*DH + q4*4];
        a0 += kf*vr.x; a1 += kf*vr.y; a2 += kf*vr.z; a3 += kf*vr.w;
        ks += kf;
    }
    float* o = &g_KVc[((b*NHEAD + h)*DH + dk)*DH + q4*4];
    o[0]=a0*invS; o[1]=a1*invS; o[2]=a2*invS; o[3]=a3*invS;
    if (q4 == 0) g_Ksc[(b*NHEAD + h)*DH + dk] = ks;
}

// ---------------- kernel 5: sim + top-8 (4 rows/block, 256 blocks) -----------
__global__ void __launch_bounds__(256) simtopk_kernel()
{
    const int b = blockIdx.x;
    const int qr0 = blockIdx.y * 4;
    const int tid = threadIdx.x;
    __shared__ float qsh[4*256];
    __shared__ float ksh[256*33];
    __shared__ float ssh[4*256];

    #pragma unroll
    for (int i = 0; i < 4; i++){
        int e = tid + i*256;
        qsh[e] = g_qm[(b*NW + qr0 + (e >> 8))*DMODEL + (e & 255)];
    }
    float acc[4] = {0.f, 0.f, 0.f, 0.f};

    for (int ct = 0; ct < 8; ct++){
        __syncthreads();
        int ch0 = ct * 32;
        #pragma unroll
        for (int i = 0; i < 32; i++){
            int e = tid + i*256;
            int row = e >> 5, ch = e & 31;
            ksh[row*33 + ch] = g_km[(b*NW + row)*DMODEL + ch0 + ch];
        }
        __syncthreads();
        #pragma unroll
        for (int ch = 0; ch < 32; ch++){
            float kv = ksh[tid*33 + ch];
            #pragma unroll
            for (int r = 0; r < 4; r++)
                acc[r] += qsh[r*256 + ch0 + ch] * kv;
        }
    }
    __syncthreads();
    #pragma unroll
    for (int r = 0; r < 4; r++) ssh[r*256 + tid] = acc[r];
    __syncthreads();

    int w = tid >> 5, lane = tid & 31;
    if (w < 4){
        float* row = &ssh[w*256];
        for (int j = 0; j < TOPK; j++){
            float lv = -3.0e38f; int li = 1 << 30;
            #pragma unroll
            for (int c0 = 0; c0 < 256; c0 += 32){
                float v2 = row[c0 + lane];
                if (v2 > lv) { lv = v2; li = c0 + lane; }
            }
            #pragma unroll
            for (int off = 16; off; off >>= 1){
                float ov = __shfl_down_sync(0xffffffffu, lv, off);
                int   oi = __shfl_down_sync(0xffffffffu, li, off);
                if (ov > lv || (ov == lv && oi < li)) { lv = ov; li = oi; }
            }
            li = __shfl_sync(0xffffffffu, li, 0);
            if (lane == 0){
                g_idx[(b*NW + qr0 + w)*TOPK + j] = li;
                row[li] = -3.0e38f;
            }
            __syncwarp();
        }
    }
}

// ---------------- kernel 6: gather-sum KV + epilogue (pixel-major out) -------
__global__ void __launch_bounds__(256) attn_kernel()
{
    __shared__ float KVsh[NHEAD*DH*DH];
    __shared__ float Kssh[DMODEL];
    __shared__ float Zsh[LP*NHEAD];
    __shared__ int widx[TOPK];

    const int b  = blockIdx.x >> 8;
    const int qw = blockIdx.x & 255;
    const int mi = qw >> 4, ni = qw & 15;
    const int tid = threadIdx.x;
    const int h = tid >> 5, lane = tid & 31;

    if (tid < TOPK) widx[tid] = g_idx[(b*NW + qw)*TOPK + tid];
    __syncthreads();

    {
        float ks = g_Ksc[b*DMODEL + tid];
        #pragma unroll
        for (int j = 0; j < TOPK; j++)
            ks += g_Ksw[(b*NW + widx[j])*DMODEL + tid];
        Kssh[tid] = ks;
    }

    const float4* cb = (const float4*)g_KVc + b*2048;
    #pragma unroll
    for (int it = 0; it < 8; it++){
        int t = tid + it*256;
        float ax=0.f, ay=0.f, az=0.f, aw=0.f;
        #pragma unroll
        for (int j = 0; j < TOPK; j++){
            float4 x = *((const float4*)g_KVw + (size_t)(b*NW + widx[j])*2048 + t);
            ax += x.x; ay += x.y; az += x.z; aw += x.w;
        }
        float4 c = cb[t];
        ((float4*)KVsh)[t] = make_float4(c.x + ax, c.y + ay, c.z + az, c.w + aw);
    }
    __syncthreads();

    const size_t pxbase = (size_t)(b*NPIX + (mi*7)*WWID + ni*7);
    const float* qfbase = g_QF + pxbase*DMODEL;

    for (int pr = tid; pr < LP*NHEAD; pr += 256){
        int l = pr >> 3, hh = pr & 7;
        int r = l / 7, cc = l - r*7;
        const float* qf = qfbase + (size_t)(r*WWID + cc)*DMODEL + hh*DH;
        float dot = 0.f;
        #pragma unroll
        for (int t = 0; t < 8; t++){
            float4 q4 = *(const float4*)(qf + t*4);
            const float* kr = &Kssh[hh*DH + t*4];
            dot += q4.x*kr[0] + q4.y*kr[1] + q4.z*kr[2] + q4.w*kr[3];
        }
        Zsh[l*NHEAD + hh] = 1.f/(dot + EPSI);
    }
    __syncthreads();

    {
        unsigned long long kvc[16];
        #pragma unroll
        for (int t = 0; t < 16; t++)
            kvc[t] = pk2(KVsh[(h*DH + 2*t)*DH + lane],
                         KVsh[(h*DH + 2*t+1)*DH + lane]);

        float* ob = g_OUT + pxbase*DMODEL + tid;
        #pragma unroll
        for (int r = 0; r < 7; r++){
            #pragma unroll
            for (int cc = 0; cc < 7; cc++){
                int l = r*7 + cc;
                const float* qf = qfbase + (size_t)(r*WWID + cc)*DMODEL + h*DH;
                unsigned long long a2 = 0ull;
                #pragma unroll
                for (int t = 0; t < 8; t++){
                    float4 q4 = *(const float4*)(qf + t*4);
                    fma2(a2, pk2(q4.x, q4.y), kvc[2*t]);
                    fma2(a2, pk2(q4.z, q4.w), kvc[2*t+1]);
                }
                float2 p2 = upk2(a2);
                ob[(size_t)(r*WWID + cc)*DMODEL] =
                    (p2.x + p2.y) * Zsh[l*NHEAD + h] * (float)SS;
            }
        }
    }
}

// ---------------- kernel 7: out-transpose [b][px][ch] -> [b][ch][px] ---------
// grid (392, 4) block 256
__global__ void __launch_bounds__(256) transpose_out_kernel(float* __restrict__ out)
{
    const int b = blockIdx.y;
    const int px0 = blockIdx.x * 32;
    __shared__ float s[256*33];
    const int tid = threadIdx.x;

    #pragma unroll
    for (int i = 0; i < 32; i++){
        int e = tid + i*256;
        int px = e >> 8, ch = e & 255;
        s[ch*33 + px] = g_OUT[(size_t)(b*NPIX + px0 + px)*DMODEL + ch];
    }
    __syncthreads();
    #pragma unroll
    for (int i = 0; i < 32; i++){
        int e = tid + i*256;
        int ch = e >> 5, px = e & 31;
        out[(size_t)(b*DMODEL + ch)*NPIX + px0 + px] = s[ch*33 + px];
    }
}

// ---------------- launch ------------------------------------------------------
extern "C" void kernel_launch(void* const* d_in, const int* in_sizes, int n_in,
                              void* d_out, int out_size)
{
    const float* q = (const float*)d_in[0];
    const float* k = (const float*)d_in[1];
    const float* v = (const float*)d_in[2];
    float* out = (float*)d_out;

    transpose_in_kernel<<<dim3(NPIX/32, BATCH, 3), 256>>>(q, k, v);
    means_kernel<<<dim3(2048, 3), 256>>>(q, k, v);
    windowkv_kernel<<<BATCH*NW, 256>>>();
    coarse_kernel<<<32, 256>>>();
    simtopk_kernel<<<dim3(BATCH, 64), 256>>>();
    attn_kernel<<<BATCH*NW, 256>>>();
    transpose_out_kernel<<<dim3(NPIX/32, BATCH), 256>>>(out);
}

// round 5
// speedup vs baseline: 1.5296x; 1.2139x over previous
#include <cuda_runtime.h>
#include <cstdint>

#define BATCH 4
#define DMODEL 256
#define HH 112
#define WWID 112
#define NPIX (HH*WWID)    // 12544
#define NW 256
#define LP 49
#define TOPK 8
#define NHEAD 8
#define DH 32
#define SS 648
#define EPSI 1e-6f

// ---------------- scratch (pixel-major [b][px][256]) ----------------
__device__ float g_QF[(size_t)BATCH*NPIX*DMODEL];   // elu(q)+1
__device__ float g_KF[(size_t)BATCH*NPIX*DMODEL];   // elu(k)+1
__device__ float g_VN[(size_t)BATCH*NPIX*DMODEL];   // v/S
__device__ float g_OUT[(size_t)BATCH*NPIX*DMODEL];  // msg, pixel-major
__device__ float g_qm[BATCH*NW*DMODEL];
__device__ float g_km[BATCH*NW*DMODEL];
__device__ float g_vm[BATCH*NW*DMODEL];
__device__ float g_KVw[(size_t)BATCH*NW*NHEAD*DH*DH];  // per-window KV (v/S side)
__device__ float g_Ksw[BATCH*NW*DMODEL];               // per-window kf sums
__device__ float g_KVc[BATCH*NHEAD*DH*DH];             // coarse KV (already /S)
__device__ float g_Ksc[BATCH*NHEAD*DH];                // coarse kf sum
__device__ float g_KVp[BATCH*NHEAD*8*DH*DH];           // coarse partials
__device__ float g_Ksp[BATCH*NHEAD*8*DH];
__device__ int   g_idx[BATCH*NW*TOPK];

// ---------------- helpers ----------------
__device__ __forceinline__ unsigned long long pk2(float lo, float hi){
    unsigned long long r;
    asm("mov.b64 %0, {%1, %2};" : "=l"(r) : "f"(lo), "f"(hi));
    return r;
}
__device__ __forceinline__ float2 upk2(unsigned long long x){
    float2 r;
    asm("mov.b64 {%0, %1}, %2;" : "=f"(r.x), "=f"(r.y) : "l"(x));
    return r;
}
__device__ __forceinline__ void fma2(unsigned long long &d, unsigned long long a, unsigned long long b){
    asm("fma.rn.f32x2 %0, %1, %2, %0;" : "+l"(d) : "l"(a), "l"(b));
}
__device__ __forceinline__ void add2(unsigned long long &d, unsigned long long a){
    asm("add.rn.f32x2 %0, %0, %1;" : "+l"(d) : "l"(a));
}
__device__ __forceinline__ float elu1(float x){
    return (x > 0.f) ? x + 1.f : __expf(x);
}

// ---------------- kernel 1: in-transpose [b][ch][px] -> [b][px][ch] + transform
__global__ void __launch_bounds__(256) transpose_in_kernel(
    const float* __restrict__ q, const float* __restrict__ k,
    const float* __restrict__ v)
{
    const int mode = blockIdx.z, b = blockIdx.y;
    const int px0 = blockIdx.x * 32;
    const float* src = (mode == 0) ? q : (mode == 1) ? k : v;
    float* dst = (mode == 0) ? g_QF : (mode == 1) ? g_KF : g_VN;

    __shared__ float s[256*33];
    const int tid = threadIdx.x;
    const float invS = 1.f/(float)SS;

    #pragma unroll
    for (int i = 0; i < 8; i++){
        int e = tid + i*256;
        int ch = e >> 3, px4 = (e & 7) * 4;
        float4 x = *(const float4*)(src + (size_t)(b*DMODEL + ch)*NPIX + px0 + px4);
        float f0, f1, f2, f3;
        if (mode == 2){ f0 = x.x*invS; f1 = x.y*invS; f2 = x.z*invS; f3 = x.w*invS; }
        else { f0 = elu1(x.x); f1 = elu1(x.y); f2 = elu1(x.z); f3 = elu1(x.w); }
        s[ch*33 + px4 + 0] = f0;
        s[ch*33 + px4 + 1] = f1;
        s[ch*33 + px4 + 2] = f2;
        s[ch*33 + px4 + 3] = f3;
    }
    __syncthreads();
    #pragma unroll
    for (int i = 0; i < 32; i++){
        int e = tid + i*256;
        int px = e >> 8, ch = e & 255;
        dst[(size_t)(b*NPIX + px0 + px)*DMODEL + ch] = s[ch*33 + px];
    }
}

// ---------------- kernel 2: raw window means (q, k only) --------------------
#define SP 792
__global__ void means_kernel(const float* __restrict__ q,
                             const float* __restrict__ k)
{
    const int mode = blockIdx.y;
    const int bx = blockIdx.x;
    const int chnk = bx & 31;
    const int wi   = (bx >> 5) & 15;
    const int b    = bx >> 9;
    const int ch0  = chnk * 8;
    const float* src = (mode == 0) ? q : k;
    float* dstm = (mode == 0) ? g_qm : g_km;

    __shared__ float s[8*SP];
    const int tid = threadIdx.x;

    for (int e = tid; e < 8*196; e += 256){
        int ch = e / 196, i4 = e - ch*196;
        const float4* gp = (const float4*)(src + (size_t)(b*DMODEL + ch0 + ch)*NPIX
                                           + (size_t)wi*784) + i4;
        *(float4*)&s[ch*SP + i4*4] = *gp;
    }
    __syncthreads();

    if (tid < 128){
        int ch = tid & 7, wj = tid >> 3;
        float sum = 0.f;
        #pragma unroll
        for (int r = 0; r < 7; r++)
            #pragma unroll
            for (int cc = 0; cc < 7; cc++)
                sum += s[ch*SP + r*112 + wj*7 + cc];
        dstm[(b*NW + wi*16 + wj)*DMODEL + ch0 + ch] = sum * (1.f/49.f);
    }
}

// ---------------- kernel 3: per-window KV + Ksum + vm -----------------------
__global__ void __launch_bounds__(256) windowkv_kernel()
{
    const int bw = blockIdx.x;
    const int b = bw >> 8, w = bw & 255;
    const int mi = w >> 4, ni = w & 15;
    const int tid = threadIdx.x;
    const int h = tid >> 5, lane = tid & 31;
    const int dk0 = (lane >> 2) * 4, dv0 = (lane & 3) * 8;

    const size_t base = (size_t)(b*NPIX + (mi*7)*WWID + ni*7) * DMODEL;
    const float* kf = g_KF + base + h*DH + dk0;
    const float* vn = g_VN + base + h*DH + dv0;

    unsigned long long acc[4][4];
    #pragma unroll
    for (int i = 0; i < 4; i++)
        #pragma unroll
        for (int j = 0; j < 4; j++) acc[i][j] = 0ull;
    unsigned long long vs[4] = {0ull, 0ull, 0ull, 0ull};
    float s0=0.f, s1=0.f, s2=0.f, s3=0.f;

    #pragma unroll
    for (int r = 0; r < 7; r++){
        #pragma unroll
        for (int cc = 0; cc < 7; cc++){
            const size_t off = (size_t)(r*WWID + cc)*DMODEL;
            float4 kf4 = *(const float4*)(kf + off);
            ulonglong2 va = *(const ulonglong2*)(vn + off);
            ulonglong2 vb = *(const ulonglong2*)(vn + off + 4);
            unsigned long long kp;
            kp = pk2(kf4.x, kf4.x);
            fma2(acc[0][0], kp, va.x); fma2(acc[0][1], kp, va.y);
            fma2(acc[0][2], kp, vb.x); fma2(acc[0][3], kp, vb.y);
            kp = pk2(kf4.y, kf4.y);
            fma2(acc[1][0], kp, va.x); fma2(acc[1][1], kp, va.y);
            fma2(acc[1][2], kp, vb.x); fma2(acc[1][3], kp, vb.y);
            kp = pk2(kf4.z, kf4.z);
            fma2(acc[2][0], kp, va.x); fma2(acc[2][1], kp, va.y);
            fma2(acc[2][2], kp, vb.x); fma2(acc[2][3], kp, vb.y);
            kp = pk2(kf4.w, kf4.w);
            fma2(acc[3][0], kp, va.x); fma2(acc[3][1], kp, va.y);
            fma2(acc[3][2], kp, vb.x); fma2(acc[3][3], kp, vb.y);
            s0 += kf4.x; s1 += kf4.y; s2 += kf4.z; s3 += kf4.w;
            add2(vs[0], va.x); add2(vs[1], va.y);
            add2(vs[2], vb.x); add2(vs[3], vb.y);
        }
    }

    float* o = g_KVw + (size_t)bw*(NHEAD*DH*DH) + h*DH*DH + dk0*DH + dv0;
    #pragma unroll
    for (int i = 0; i < 4; i++)
        #pragma unroll
        for (int j = 0; j < 4; j++){
            float2 t = upk2(acc[i][j]);
            *(float2*)(o + i*DH + 2*j) = t;
        }
    if ((lane & 3) == 0){
        float* ks = g_Ksw + bw*DMODEL + h*DH + dk0;
        ks[0]=s0; ks[1]=s1; ks[2]=s2; ks[3]=s3;
    }
    if (dk0 == 0){
        // vm raw-mean = (S/49) * Sum_p VN
        const float f = (float)SS/49.f;
        float* vmp = g_vm + bw*DMODEL + h*DH + dv0;
        #pragma unroll
        for (int j = 0; j < 4; j++){
            float2 t = upk2(vs[j]);
            vmp[2*j]   = t.x * f;
            vmp[2*j+1] = t.y * f;
        }
    }
}

// ---------------- kernel 4a: coarse partials (grid 32 x 8) ------------------
__global__ void coarse_part_kernel()
{
    const int bh = blockIdx.x;          // b*8 + h
    const int split = blockIdx.y;       // 0..7
    const int b = bh >> 3, h = bh & 7;
    const int tid = threadIdx.x;
    const int dk = tid >> 3, q4 = tid & 7;
    float a0=0.f,a1=0.f,a2=0.f,a3=0.f, ks=0.f;
    const int w0 = split * 32;
    #pragma unroll 4
    for (int w = w0; w < w0 + 32; w++){
        float kraw = g_km[(b*NW + w)*DMODEL + h*DH + dk];
        float kf = elu1(kraw);
        float4 vr = *(const float4*)&g_vm[(b*NW + w)*DMODEL + h*DH + q4*4];
        a0 += kf*vr.x; a1 += kf*vr.y; a2 += kf*vr.z; a3 += kf*vr.w;
        ks += kf;
    }
    float* o = &g_KVp[((bh*8 + split)*DH + dk)*DH + q4*4];
    o[0]=a0; o[1]=a1; o[2]=a2; o[3]=a3;
    if (q4 == 0) g_Ksp[(bh*8 + split)*DH + dk] = ks;
}

// ---------------- kernel 4b: coarse reduce (grid 32) ------------------------
__global__ void coarse_reduce_kernel()
{
    const int bh = blockIdx.x;
    const int tid = threadIdx.x;
    const int dk = tid >> 3, q4 = tid & 7;
    const float invS = 1.f/(float)SS;
    float a0=0.f,a1=0.f,a2=0.f,a3=0.f;
    #pragma unroll
    for (int s = 0; s < 8; s++){
        float4 x = *(const float4*)&g_KVp[((bh*8 + s)*DH + dk)*DH + q4*4];
        a0 += x.x; a1 += x.y; a2 += x.z; a3 += x.w;
    }
    float* o = &g_KVc[(bh*DH + dk)*DH + q4*4];
    o[0]=a0*invS; o[1]=a1*invS; o[2]=a2*invS; o[3]=a3*invS;
    if (q4 == 0){
        float ks = 0.f;
        #pragma unroll
        for (int s = 0; s < 8; s++) ks += g_Ksp[(bh*8 + s)*DH + dk];
        g_Ksc[bh*DH + dk] = ks;
    }
}

// ---------------- kernel 5: sim + top-8 (4 rows/block) -----------------------
__global__ void __launch_bounds__(256) simtopk_kernel()
{
    const int b = blockIdx.x;
    const int qr0 = blockIdx.y * 4;
    const int tid = threadIdx.x;
    __shared__ float qsh[4*256];
    __shared__ float ksh[256*33];
    __shared__ float ssh[4*256];

    #pragma unroll
    for (int i = 0; i < 4; i++){
        int e = tid + i*256;
        qsh[e] = g_qm[(b*NW + qr0 + (e >> 8))*DMODEL + (e & 255)];
    }
    float acc[4] = {0.f, 0.f, 0.f, 0.f};

    for (int ct = 0; ct < 8; ct++){
        __syncthreads();
        int ch0 = ct * 32;
        #pragma unroll
        for (int i = 0; i < 32; i++){
            int e = tid + i*256;
            int row = e >> 5, ch = e & 31;
            ksh[row*33 + ch] = g_km[(b*NW + row)*DMODEL + ch0 + ch];
        }
        __syncthreads();
        #pragma unroll
        for (int ch = 0; ch < 32; ch++){
            float kv = ksh[tid*33 + ch];
            #pragma unroll
            for (int r = 0; r < 4; r++)
                acc[r] += qsh[r*256 + ch0 + ch] * kv;
        }
    }
    __syncthreads();
    #pragma unroll
    for (int r = 0; r < 4; r++) ssh[r*256 + tid] = acc[r];
    __syncthreads();

    int w = tid >> 5, lane = tid & 31;
    if (w < 4){
        float* row = &ssh[w*256];
        for (int j = 0; j < TOPK; j++){
            float lv = -3.0e38f; int li = 1 << 30;
            #pragma unroll
            for (int c0 = 0; c0 < 256; c0 += 32){
                float v2 = row[c0 + lane];
                if (v2 > lv) { lv = v2; li = c0 + lane; }
            }
            #pragma unroll
            for (int off = 16; off; off >>= 1){
                float ov = __shfl_down_sync(0xffffffffu, lv, off);
                int   oi = __shfl_down_sync(0xffffffffu, li, off);
                if (ov > lv || (ov == lv && oi < li)) { lv = ov; li = oi; }
            }
            li = __shfl_sync(0xffffffffu, li, 0);
            if (lane == 0){
                g_idx[(b*NW + qr0 + w)*TOPK + j] = li;
                row[li] = -3.0e38f;
            }
            __syncwarp();
        }
    }
}

// ---------------- kernel 6: gather-sum KV + epilogue -------------------------
__global__ void __launch_bounds__(256) attn_kernel()
{
    __shared__ float KVsh[NHEAD*DH*DH];
    __shared__ float Kssh[DMODEL];
    __shared__ float Zsh[LP*NHEAD];
    __shared__ int widx[TOPK];

    const int b  = blockIdx.x >> 8;
    const int qw = blockIdx.x & 255;
    const int mi = qw >> 4, ni = qw & 15;
    const int tid = threadIdx.x;
    const int h = tid >> 5, lane = tid & 31;

    if (tid < TOPK) widx[tid] = g_idx[(b*NW + qw)*TOPK + tid];
    __syncthreads();

    {
        float ks = g_Ksc[b*DMODEL + tid];
        #pragma unroll
        for (int j = 0; j < TOPK; j++)
            ks += g_Ksw[(b*NW + widx[j])*DMODEL + tid];
        Kssh[tid] = ks;
    }

    const float4* cb = (const float4*)g_KVc + b*2048;
    #pragma unroll
    for (int it = 0; it < 8; it++){
        int t = tid + it*256;
        float ax=0.f, ay=0.f, az=0.f, aw=0.f;
        #pragma unroll
        for (int j = 0; j < TOPK; j++){
            float4 x = *((const float4*)g_KVw + (size_t)(b*NW + widx[j])*2048 + t);
            ax += x.x; ay += x.y; az += x.z; aw += x.w;
        }
        float4 c = cb[t];
        ((float4*)KVsh)[t] = make_float4(c.x + ax, c.y + ay, c.z + az, c.w + aw);
    }
    __syncthreads();

    const size_t pxbase = (size_t)(b*NPIX + (mi*7)*WWID + ni*7);
    const float* qfbase = g_QF + pxbase*DMODEL;

    for (int pr = tid; pr < LP*NHEAD; pr += 256){
        int l = pr >> 3, hh = pr & 7;
        int r = l / 7, cc = l - r*7;
        const float* qf = qfbase + (size_t)(r*WWID + cc)*DMODEL + hh*DH;
        float dot = 0.f;
        #pragma unroll
        for (int t = 0; t < 8; t++){
            float4 q4 = *(const float4*)(qf + t*4);
            const float* kr = &Kssh[hh*DH + t*4];
            dot += q4.x*kr[0] + q4.y*kr[1] + q4.z*kr[2] + q4.w*kr[3];
        }
        Zsh[l*NHEAD + hh] = 1.f/(dot + EPSI);
    }
    __syncthreads();

    {
        unsigned long long kvc[16];
        #pragma unroll
        for (int t = 0; t < 16; t++)
            kvc[t] = pk2(KVsh[(h*DH + 2*t)*DH + lane],
                         KVsh[(h*DH + 2*t+1)*DH + lane]);

        float* ob = g_OUT + pxbase*DMODEL + tid;
        #pragma unroll
        for (int r = 0; r < 7; r++){
            #pragma unroll
            for (int cc = 0; cc < 7; cc++){
                int l = r*7 + cc;
                const float* qf = qfbase + (size_t)(r*WWID + cc)*DMODEL + h*DH;
                unsigned long long a2 = 0ull;
                #pragma unroll
                for (int t = 0; t < 8; t++){
                    float4 q4 = *(const float4*)(qf + t*4);
                    fma2(a2, pk2(q4.x, q4.y), kvc[2*t]);
                    fma2(a2, pk2(q4.z, q4.w), kvc[2*t+1]);
                }
                float2 p2 = upk2(a2);
                ob[(size_t)(r*WWID + cc)*DMODEL] =
                    (p2.x + p2.y) * Zsh[l*NHEAD + h] * (float)SS;
            }
        }
    }
}

// ---------------- kernel 7: out-transpose ------------------------------------
__global__ void __launch_bounds__(256) transpose_out_kernel(float* __restrict__ out)
{
    const int b = blockIdx.y;
    const int px0 = blockIdx.x * 32;
    __shared__ float s[256*33];
    const int tid = threadIdx.x;

    #pragma unroll
    for (int i = 0; i < 32; i++){
        int e = tid + i*256;
        int px = e >> 8, ch = e & 255;
        s[ch*33 + px] = g_OUT[(size_t)(b*NPIX + px0 + px)*DMODEL + ch];
    }
    __syncthreads();
    #pragma unroll
    for (int i = 0; i < 32; i++){
        int e = tid + i*256;
        int ch = e >> 5, px = e & 31;
        out[(size_t)(b*DMODEL + ch)*NPIX + px0 + px] = s[ch*33 + px];
    }
}

// ---------------- launch ------------------------------------------------------
extern "C" void kernel_launch(void* const* d_in, const int* in_sizes, int n_in,
                              void* d_out, int out_size)
{
    const float* q = (const float*)d_in[0];
    const float* k = (const float*)d_in[1];
    const float* v = (const float*)d_in[2];
    float* out = (float*)d_out;

    transpose_in_kernel<<<dim3(NPIX/32, BATCH, 3), 256>>>(q, k, v);
    means_kernel<<<dim3(2048, 2), 256>>>(q, k);
    windowkv_kernel<<<BATCH*NW, 256>>>();
    coarse_part_kernel<<<dim3(32, 8), 256>>>();
    coarse_reduce_kernel<<<32, 256>>>();
    simtopk_kernel<<<dim3(BATCH, 64), 256>>>();
    attn_kernel<<<BATCH*NW, 256>>>();
    transpose_out_kernel<<<dim3(NPIX/32, BATCH), 256>>>(out);
}